// round 15
// baseline (speedup 1.0000x reference)
#include <cuda_runtime.h>
#include <cuda_bf16.h>
#include <cuda_fp16.h>
#include <math.h>

#define TD 128
#define MAXN 50000
#define MAXE 1600000
#define MAXG 64
#define SCAN_B 256
#define MAXBLK ((MAXN + SCAN_B - 1) / SCAN_B)
#define AGGF 0x40000000u
#define PREF 0x80000000u
#define VMSK 0x3FFFFFFFu

// ---------------- scratch (static device globals; no allocations) -------------
__device__ __half g_Ah[MAXN * TD];       // GEMM output, rows pre-scaled by disq
__device__ __half g_Bh[MAXN * TD];       // gather output (pre-relu)
__device__ int   g_cnt[MAXN];
__device__ float g_disq[MAXN];
__device__ int   g_rowptr[MAXN + 1];
__device__ int   g_cursor[MAXN];
__device__ int   g_csr[MAXE];
__device__ unsigned g_stat[MAXBLK];      // lookback status: value | AGGF/PREF
__device__ float g_sums[MAXG * TD];
__device__ float g_gcnt[MAXG];
__device__ __nv_bfloat16 g_wh[3][TD * TD];   // W^T hi planes, [n][k] compact
__device__ __nv_bfloat16 g_wl[3][TD * TD];   // W^T lo planes

// ---------------- persistent stream/events (created pre-main; no device mem) ---
static cudaStream_t g_s2;
static cudaEvent_t g_evF, g_evD, g_evJ;
struct _InitOnce {
    _InitOnce() {
        cudaStreamCreateWithFlags(&g_s2, cudaStreamNonBlocking);
        cudaEventCreateWithFlags(&g_evF, cudaEventDisableTiming);
        cudaEventCreateWithFlags(&g_evD, cudaEventDisableTiming);
        cudaEventCreateWithFlags(&g_evJ, cudaEventDisableTiming);
    }
};
static _InitOnce _init_once;

// ---------------- fused init: zero cnt + pooled sums + gcnt + scan status ------
__global__ void k_init(int* __restrict__ cnt, float* __restrict__ sums,
                       float* __restrict__ gcnt, unsigned* __restrict__ stat,
                       int N, int G, int nb) {
    int i = blockIdx.x * blockDim.x + threadIdx.x;
    if (i < N) cnt[i] = 0;
    if (i < G * TD) sums[i] = 0.f;
    if (i < G) gcnt[i] = 0.f;
    if (i < nb) stat[i] = 0u;
}

// 4 edges per thread (MLP=4)
__global__ void k_count(const int* __restrict__ ei, int* __restrict__ cnt,
                        int E, int vec_ok) {
    int e0 = (blockIdx.x * blockDim.x + threadIdx.x) * 4;
    if (vec_ok && e0 + 3 < E) {
        int4 d = *(const int4*)(ei + E + e0);
        atomicAdd(&cnt[d.x], 1);
        atomicAdd(&cnt[d.y], 1);
        atomicAdd(&cnt[d.z], 1);
        atomicAdd(&cnt[d.w], 1);
    } else {
        #pragma unroll
        for (int q = 0; q < 4; q++)
            if (e0 + q < E) atomicAdd(&cnt[ei[E + e0 + q]], 1);
    }
}

// single-kernel decoupled-lookback exclusive scan (warp-parallel lookback)
__global__ void k_scan_lb(const int* __restrict__ cnt, int* __restrict__ rowptr,
                          int* __restrict__ cursor, float* __restrict__ disq,
                          const int* __restrict__ batch, float* __restrict__ gcnt,
                          unsigned* __restrict__ stat, int N, int nb) {
    __shared__ int wsum[8];
    __shared__ int s_exc;
    int t = threadIdx.x, bid = blockIdx.x;
    int i = bid * SCAN_B + t;
    int lane = t & 31, wid = t >> 5;

    int v = (i < N) ? cnt[i] : 0;
    if (i < N) disq[i] = rsqrtf((float)(v + 1));

    int inc = v;
    #pragma unroll
    for (int off = 1; off < 32; off <<= 1) {
        int u = __shfl_up_sync(0xffffffffu, inc, off);
        if (lane >= off) inc += u;
    }
    if (lane == 31) wsum[wid] = inc;
    __syncthreads();
    if (wid == 0) {
        int w = (lane < 8) ? wsum[lane] : 0;
        #pragma unroll
        for (int off = 1; off < 8; off <<= 1) {
            int u = __shfl_up_sync(0xffffffffu, w, off);
            if (lane >= off) w += u;
        }
        if (lane < 8) wsum[lane] = w;
    }
    __syncthreads();
    int base = (wid > 0) ? wsum[wid - 1] : 0;
    int total = wsum[7];

    if (wid == 0) {
        if (bid == 0) {
            if (lane == 0) {
                atomicExch(&stat[0], (unsigned)total | PREF);
                s_exc = 0;
            }
        } else {
            if (lane == 0) atomicExch(&stat[bid], (unsigned)total | AGGF);
            __syncwarp();
            int exc = 0;
            int p_hi = bid - 1;
            while (true) {
                int idx = p_hi - lane;
                unsigned s = (idx >= 0) ? *(volatile unsigned*)&stat[idx] : PREF;
                bool ready = (s & (AGGF | PREF)) != 0u;
                if (__ballot_sync(0xffffffffu, ready) != 0xffffffffu) continue;
                unsigned pm = __ballot_sync(0xffffffffu, (s & PREF) != 0u);
                if (pm) {
                    int first = __ffs(pm) - 1;
                    int contrib = (lane <= first) ? (int)(s & VMSK) : 0;
                    #pragma unroll
                    for (int off = 16; off; off >>= 1)
                        contrib += __shfl_down_sync(0xffffffffu, contrib, off);
                    exc += __shfl_sync(0xffffffffu, contrib, 0);
                    break;
                } else {
                    int contrib = (int)(s & VMSK);
                    #pragma unroll
                    for (int off = 16; off; off >>= 1)
                        contrib += __shfl_down_sync(0xffffffffu, contrib, off);
                    exc += __shfl_sync(0xffffffffu, contrib, 0);
                    p_hi -= 32;
                }
            }
            if (lane == 0) {
                atomicExch(&stat[bid], (unsigned)(exc + total) | PREF);
                s_exc = exc;
            }
        }
    }
    __syncthreads();
    int exc = s_exc;

    if (i < N) {
        int r = exc + base + inc - v;
        rowptr[i] = r;
        cursor[i] = r;
    }
    if (bid == nb - 1 && t == 0) rowptr[N] = exc + total;

    int g = (i < N) ? __ldg(&batch[i]) : -1;
    int g0 = __shfl_sync(0xffffffffu, g, 0);
    bool uni = __all_sync(0xffffffffu, g == g0);
    if (uni) {
        if (lane == 0 && g0 >= 0) {
            int base2 = bid * SCAN_B + (t & ~31);
            int cntw = min(N - base2, 32);
            asm volatile("red.global.add.f32 [%0], %1;" :: "l"(gcnt + g0), "f"((float)cntw) : "memory");
        }
    } else if (g >= 0) {
        asm volatile("red.global.add.f32 [%0], %1;" :: "l"(gcnt + g), "f"(1.0f) : "memory");
    }
}

// 4 edges per thread (MLP=4)
__global__ void k_fill(const int* __restrict__ ei, int* __restrict__ cursor,
                       int* __restrict__ csr, int E, int vec_ok) {
    int e0 = (blockIdx.x * blockDim.x + threadIdx.x) * 4;
    if (vec_ok && e0 + 3 < E) {
        int4 s = *(const int4*)(ei + e0);
        int4 d = *(const int4*)(ei + E + e0);
        int p0 = atomicAdd(&cursor[d.x], 1);
        int p1 = atomicAdd(&cursor[d.y], 1);
        int p2 = atomicAdd(&cursor[d.z], 1);
        int p3 = atomicAdd(&cursor[d.w], 1);
        csr[p0] = s.x; csr[p1] = s.y; csr[p2] = s.z; csr[p3] = s.w;
    } else {
        #pragma unroll
        for (int q = 0; q < 4; q++) {
            int e = e0 + q;
            if (e < E) {
                int pos = atomicAdd(&cursor[ei[E + e]], 1);
                csr[pos] = ei[e];
            }
        }
    }
}

// ---------------- W split/transpose prep -----------------------------------
__global__ void k_wprep3(const float* __restrict__ W1, const float* __restrict__ W2,
                         const float* __restrict__ W3, __nv_bfloat16* __restrict__ hi,
                         __nv_bfloat16* __restrict__ lo) {
    int idx = blockIdx.x * blockDim.x + threadIdx.x;
    int l = idx >> 14;
    int r = idx & 16383;
    const float* W = (l == 0) ? W1 : (l == 1) ? W2 : W3;
    int k = r >> 7, n = r & 127;
    float v = W[r];
    __nv_bfloat16 h = __float2bfloat16_rn(v);
    hi[l * 16384 + n * TD + k] = h;
    lo[l * 16384 + n * TD + k] = __float2bfloat16_rn(v - __bfloat162float(h));
}

// ---------------- gather: half-warp rows, LDG.128, fp32 accum -------------------
__device__ __forceinline__ void add8(float* a, uint4 r) {
    half2* hp = (half2*)&r;
    #pragma unroll
    for (int i = 0; i < 4; i++) {
        float2 f = __half22float2(hp[i]);
        a[2 * i] += f.x;
        a[2 * i + 1] += f.y;
    }
}

// computes 8 features [8*(lane&15) .. +8) of:
// disq[w]*(sum_{src in N(w)} h'[src] + h'[w]) + bias   (pre-relu)
// all 32 lanes end with the same per-lh result (halves reduced via shfl_xor 16)
__device__ __forceinline__ void agg_node8(const __half* __restrict__ h,
                                          const int* __restrict__ rowptr,
                                          const int* __restrict__ csr,
                                          const float* __restrict__ disq,
                                          const float* __restrict__ bias,
                                          int w, int lane, float* r8) {
    int beg = __ldg(&rowptr[w]);
    int end = __ldg(&rowptr[w + 1]);
    float dd = __ldg(&disq[w]);
    int hl = lane >> 4;
    int c = (lane & 15) * 8;     // 8 fp16 features per lane

    float a0[8] = {0,0,0,0,0,0,0,0};
    float a1[8] = {0,0,0,0,0,0,0,0};

    // self row: both halves load (same addr), only half 0 accumulates
    uint4 sraw = *(const uint4*)(h + (long)w * TD + c);
    if (hl == 0) add8(a0, sraw);

    for (int base = beg; base < end; base += 32) {
        int e = base + lane;
        int sidx = (e < end) ? __ldg(&csr[e]) : 0;
        int m = end - base; if (m > 32) m = 32;
        int j = 0;
        // 8 neighbors per step: 4 LDG.128 in flight per lane
        for (; j + 7 < m; j += 8) {
            int sr[4]; uint4 vv[4];
            #pragma unroll
            for (int q = 0; q < 4; q++) {
                int s0 = __shfl_sync(0xffffffffu, sidx, j + 2 * q);
                int s1 = __shfl_sync(0xffffffffu, sidx, j + 2 * q + 1);
                sr[q] = hl ? s1 : s0;
            }
            #pragma unroll
            for (int q = 0; q < 4; q++)
                vv[q] = *(const uint4*)(h + (long)sr[q] * TD + c);
            add8(a0, vv[0]); add8(a1, vv[1]);
            add8(a0, vv[2]); add8(a1, vv[3]);
        }
        // pair tail
        for (; j + 1 < m; j += 2) {
            int s0 = __shfl_sync(0xffffffffu, sidx, j);
            int s1 = __shfl_sync(0xffffffffu, sidx, j + 1);
            int sr = hl ? s1 : s0;
            uint4 v = *(const uint4*)(h + (long)sr * TD + c);
            add8(a0, v);
        }
        // single tail
        if (j < m) {
            int s0 = __shfl_sync(0xffffffffu, sidx, j);
            uint4 v = *(const uint4*)(h + (long)s0 * TD + c);
            if (hl == 0) add8(a0, v);
        }
    }

    float4 b0 = *(const float4*)(bias + c);
    float4 b1 = *(const float4*)(bias + c + 4);
    float bb[8] = {b0.x, b0.y, b0.z, b0.w, b1.x, b1.y, b1.z, b1.w};
    #pragma unroll
    for (int i = 0; i < 8; i++) {
        float s = a0[i] + a1[i];
        s += __shfl_xor_sync(0xffffffffu, s, 16);   // combine halves
        r8[i] = fmaf(s, dd, bb[i]);
    }
}

// gather -> fp16 output (pre-relu; relu applied at next GEMM load)
__global__ void k_gather(const __half* __restrict__ h, const int* __restrict__ rowptr,
                         const int* __restrict__ csr, const float* __restrict__ disq,
                         const float* __restrict__ bias, __half* __restrict__ out, int N) {
    int w = (blockIdx.x * blockDim.x + threadIdx.x) >> 5;
    int lane = threadIdx.x & 31;
    if (w >= N) return;
    float r8[8];
    agg_node8(h, rowptr, csr, disq, bias, w, lane, r8);
    if ((lane >> 4) == 0) {
        int c = (lane & 15) * 8;
        uint4 o;
        half2 h0 = __float22half2_rn(make_float2(r8[0], r8[1]));
        half2 h1 = __float22half2_rn(make_float2(r8[2], r8[3]));
        half2 h2 = __float22half2_rn(make_float2(r8[4], r8[5]));
        half2 h3 = __float22half2_rn(make_float2(r8[6], r8[7]));
        o.x = *(unsigned*)&h0; o.y = *(unsigned*)&h1;
        o.z = *(unsigned*)&h2; o.w = *(unsigned*)&h3;
        *(uint4*)(out + (long)w * TD + c) = o;
    }
}

// layer-3 variant: accumulate straight into pooled fp32 sums
__global__ void k_gather_pool(const __half* __restrict__ h, const int* __restrict__ rowptr,
                              const int* __restrict__ csr, const float* __restrict__ disq,
                              const float* __restrict__ bias, const int* __restrict__ batch,
                              float* __restrict__ sums, int N) {
    int w = (blockIdx.x * blockDim.x + threadIdx.x) >> 5;
    int lane = threadIdx.x & 31;
    if (w >= N) return;
    float r8[8];
    agg_node8(h, rowptr, csr, disq, bias, w, lane, r8);
    if ((lane >> 4) == 0) {
        int g = __ldg(&batch[w]);
        int c = (lane & 15) * 8;
        float* p = sums + (long)g * TD + c;
        asm volatile("red.global.add.v4.f32 [%0], {%1, %2, %3, %4};"
                     :: "l"(p), "f"(r8[0]), "f"(r8[1]), "f"(r8[2]), "f"(r8[3]) : "memory");
        asm volatile("red.global.add.v4.f32 [%0], {%1, %2, %3, %4};"
                     :: "l"(p + 4), "f"(r8[4]), "f"(r8[5]), "f"(r8[6]), "f"(r8[7]) : "memory");
    }
}

// ---------------- tensor-core GEMM (persistent; 3-pass bf16 split) -------------
__device__ __forceinline__ unsigned pk_bf16x2(float hi, float lo) {
    unsigned d;
    asm("cvt.rn.bf16x2.f32 %0, %1, %2;" : "=r"(d) : "f"(hi), "f"(lo));
    return d;
}

__device__ __forceinline__ void mma_bf16(float* c, const unsigned* a, unsigned b0, unsigned b1) {
    asm volatile(
        "mma.sync.aligned.m16n8k16.row.col.f32.bf16.bf16.f32 "
        "{%0,%1,%2,%3}, {%4,%5,%6,%7}, {%8,%9}, {%0,%1,%2,%3};"
        : "+f"(c[0]), "+f"(c[1]), "+f"(c[2]), "+f"(c[3])
        : "r"(a[0]), "r"(a[1]), "r"(a[2]), "r"(a[3]), "r"(b0), "r"(b1));
}

__device__ __forceinline__ float4 ldx4(const float* p) { return *(const float4*)p; }
__device__ __forceinline__ float4 ldx4(const __half* p) {
    uint2 raw = *(const uint2*)p;
    float2 lo = __half22float2(*(half2*)&raw.x);
    float2 hi = __half22float2(*(half2*)&raw.y);
    return make_float4(lo.x, lo.y, hi.x, hi.y);
}

#define XS 136
#define WSZ (64 * XS)
#define WTS 136

template <typename T>
__global__ void __launch_bounds__(256) k_gemm_tc(const T* __restrict__ X,
                                                 const __nv_bfloat16* __restrict__ whg,
                                                 const __nv_bfloat16* __restrict__ wlg,
                                                 const float* __restrict__ disq,
                                                 __half* __restrict__ C,
                                                 int M, int do_relu, int tiles) {
    extern __shared__ char smraw[];
    float* xs = (float*)smraw;                                    // [64][136] fp32
    __nv_bfloat16* wh = (__nv_bfloat16*)(smraw + WSZ * 4);        // [128][136] hi (n,k)
    __nv_bfloat16* wl = wh + 128 * WTS;                           // lo plane

    int tid = threadIdx.x;

    // W planes loaded ONCE per block (persistent over row tiles)
    for (int idx = tid; idx < 2048; idx += 256) {
        int row = idx >> 4;
        int cc = (idx & 15) * 8;
        *(float4*)(wh + row * WTS + cc) = *(const float4*)(whg + row * TD + cc);
        *(float4*)(wl + row * WTS + cc) = *(const float4*)(wlg + row * TD + cc);
    }

    int warp = tid >> 5;
    int lane = tid & 31;
    int gid = lane >> 2;
    int tig = lane & 3;
    int r0 = 16 * (warp >> 1);
    int c0 = 64 * (warp & 1);

    for (int tile = blockIdx.x; tile < tiles; tile += gridDim.x) {
        int row0 = tile * 64;
        __syncthreads();    // xs free from previous iteration (also orders W load)
        for (int i = tid * 4; i < 64 * TD; i += 1024) {
            int r = i >> 7;
            int cc = i & 127;
            int gr = row0 + r;
            float4 v = make_float4(0.f, 0.f, 0.f, 0.f);
            if (gr < M) v = ldx4(X + (long)gr * TD + cc);
            if (do_relu) {
                v.x = fmaxf(v.x, 0.f); v.y = fmaxf(v.y, 0.f);
                v.z = fmaxf(v.z, 0.f); v.w = fmaxf(v.w, 0.f);
            }
            *(float4*)(xs + r * XS + cc) = v;
        }
        __syncthreads();

        float acc[8][4];
        #pragma unroll
        for (int t = 0; t < 8; t++)
            #pragma unroll
            for (int q = 0; q < 4; q++) acc[t][q] = 0.f;

        #pragma unroll
        for (int k0 = 0; k0 < TD; k0 += 16) {
            float2 p0 = *(float2*)&xs[(r0 + gid) * XS + k0 + 2 * tig];
            float2 p1 = *(float2*)&xs[(r0 + gid + 8) * XS + k0 + 2 * tig];
            float2 p2 = *(float2*)&xs[(r0 + gid) * XS + k0 + 8 + 2 * tig];
            float2 p3 = *(float2*)&xs[(r0 + gid + 8) * XS + k0 + 8 + 2 * tig];
            unsigned ah[4], al[4];
            float2 pp[4] = {p0, p1, p2, p3};
            #pragma unroll
            for (int i = 0; i < 4; i++) {
                unsigned h = pk_bf16x2(pp[i].y, pp[i].x);
                ah[i] = h;
                float hx = __uint_as_float(h << 16);
                float hy = __uint_as_float(h & 0xffff0000u);
                al[i] = pk_bf16x2(pp[i].y - hy, pp[i].x - hx);
            }
            #pragma unroll
            for (int t = 0; t < 8; t++) {
                int n = c0 + 8 * t + gid;
                unsigned bh0 = *(const unsigned*)&wh[n * WTS + k0 + 2 * tig];
                unsigned bh1 = *(const unsigned*)&wh[n * WTS + k0 + 8 + 2 * tig];
                unsigned bl0 = *(const unsigned*)&wl[n * WTS + k0 + 2 * tig];
                unsigned bl1 = *(const unsigned*)&wl[n * WTS + k0 + 8 + 2 * tig];
                mma_bf16(acc[t], ah, bh0, bh1);
                mma_bf16(acc[t], al, bh0, bh1);
                mma_bf16(acc[t], ah, bl0, bl1);
            }
        }

        int gr = row0 + r0 + gid;
        int gr2 = gr + 8;
        float s1 = (gr < M) ? __ldg(&disq[gr]) : 0.f;
        float s2 = (gr2 < M) ? __ldg(&disq[gr2]) : 0.f;
        #pragma unroll
        for (int t = 0; t < 8; t++) {
            int col = c0 + 8 * t + 2 * tig;
            if (gr < M) {
                half2 o = __float22half2_rn(make_float2(acc[t][0] * s1, acc[t][1] * s1));
                *(half2*)&C[(long)gr * TD + col] = o;
            }
            if (gr2 < M) {
                half2 o = __float22half2_rn(make_float2(acc[t][2] * s2, acc[t][3] * s2));
                *(half2*)&C[(long)gr2 * TD + col] = o;
            }
        }
    }
}

// ---------------- fused 2-layer MLP head (per-graph independent) ----------------
__global__ void k_mlp2(const float* __restrict__ in,
                       const float* __restrict__ Wm1, const float* __restrict__ bm1,
                       const float* __restrict__ Wm2, const float* __restrict__ bm2,
                       const float* __restrict__ gcnt, float* __restrict__ out) {
    __shared__ float p[TD];
    __shared__ float q[TD];
    int g = blockIdx.x, j = threadIdx.x;
    float scale = 1.0f / fmaxf(gcnt[g], 1.0f);
    p[j] = in[g * TD + j] * scale;
    __syncthreads();
    float acc = bm1[j];
    #pragma unroll 8
    for (int k = 0; k < TD; k++) acc = fmaf(p[k], Wm1[k * TD + j], acc);
    q[j] = fmaxf(acc, 0.f);
    __syncthreads();
    float acc2 = bm2[j];
    #pragma unroll 8
    for (int k = 0; k < TD; k++) acc2 = fmaf(q[k], Wm2[k * TD + j], acc2);
    out[g * TD + j] = acc2;
}

// ---------------- launch --------------------------------------------------------
extern "C" void kernel_launch(void* const* d_in, const int* in_sizes, int n_in,
                              void* d_out, int out_size) {
    const float* x   = (const float*)d_in[0];
    const float* W1  = (const float*)d_in[1];
    const float* b1  = (const float*)d_in[2];
    const float* W2  = (const float*)d_in[3];
    const float* b2  = (const float*)d_in[4];
    const float* W3  = (const float*)d_in[5];
    const float* b3  = (const float*)d_in[6];
    const float* Wm1 = (const float*)d_in[7];
    const float* bm1 = (const float*)d_in[8];
    const float* Wm2 = (const float*)d_in[9];
    const float* bm2 = (const float*)d_in[10];
    const int* ei    = (const int*)d_in[11];
    const int* batch = (const int*)d_in[12];

    int N = in_sizes[0] / TD;
    int E = in_sizes[11] / 2;
    int G = out_size / TD;
    int vec_ok = ((E & 3) == 0) ? 1 : 0;

    float *disq, *sums, *gcnt;
    __half *A, *B;
    int *cnt, *rowptr, *cursor, *csr;
    unsigned* stat;
    __nv_bfloat16 *wh, *wl;
    cudaGetSymbolAddress((void**)&A,      g_Ah);
    cudaGetSymbolAddress((void**)&B,      g_Bh);
    cudaGetSymbolAddress((void**)&cnt,    g_cnt);
    cudaGetSymbolAddress((void**)&disq,   g_disq);
    cudaGetSymbolAddress((void**)&rowptr, g_rowptr);
    cudaGetSymbolAddress((void**)&cursor, g_cursor);
    cudaGetSymbolAddress((void**)&csr,    g_csr);
    cudaGetSymbolAddress((void**)&stat,   g_stat);
    cudaGetSymbolAddress((void**)&sums,   g_sums);
    cudaGetSymbolAddress((void**)&gcnt,   g_gcnt);
    cudaGetSymbolAddress((void**)&wh,     g_wh);
    cudaGetSymbolAddress((void**)&wl,     g_wl);

    size_t smemG = (size_t)WSZ * 4 + 2 * (size_t)(128 * WTS) * 2;   // 104448 B
    cudaFuncSetAttribute(k_gemm_tc<float>, cudaFuncAttributeMaxDynamicSharedMemorySize, (int)smemG);
    cudaFuncSetAttribute(k_gemm_tc<__half>, cudaFuncAttributeMaxDynamicSharedMemorySize, (int)smemG);

    int nb = (N + SCAN_B - 1) / SCAN_B;
    int tiles = (N + 63) / 64;
    int gemm_grid = tiles < 296 ? tiles : 296;   // 2 blocks/SM persistent
    int gath_blocks = (N + 7) / 8;
    int edge4_blocks = (E + 1023) / 1024;

    // ---- fork: CSR build on side stream; W-prep on main -----------------------
    cudaEventRecord(g_evF, 0);
    cudaStreamWaitEvent(g_s2, g_evF, 0);

    k_init<<<(N + 255) / 256, 256, 0, g_s2>>>(cnt, sums, gcnt, stat, N, G, nb);
    k_count<<<edge4_blocks, 256, 0, g_s2>>>(ei, cnt, E, vec_ok);
    k_scan_lb<<<nb, SCAN_B, 0, g_s2>>>(cnt, rowptr, cursor, disq, batch, gcnt, stat, N, nb);
    cudaEventRecord(g_evD, g_s2);                         // disq ready
    k_fill<<<edge4_blocks, 256, 0, g_s2>>>(ei, cursor, csr, E, vec_ok);
    cudaEventRecord(g_evJ, g_s2);                         // CSR ready

    // main branch
    k_wprep3<<<192, 256>>>(W1, W2, W3, wh, wl);
    cudaStreamWaitEvent(0, g_evD, 0);                     // GEMM epilogue needs disq
    k_gemm_tc<float><<<gemm_grid, 256, smemG>>>(x, wh, wl, disq, A, N, 0, tiles);

    cudaStreamWaitEvent(0, g_evJ, 0);                     // gathers need CSR

    // layer 1
    k_gather<<<gath_blocks, 256>>>(A, rowptr, csr, disq, b1, B, N);
    // layer 2
    k_gemm_tc<__half><<<gemm_grid, 256, smemG>>>(B, wh + 16384, wl + 16384, disq, A, N, 1, tiles);
    k_gather<<<gath_blocks, 256>>>(A, rowptr, csr, disq, b2, B, N);
    // layer 3: gather fused with mean-pool accumulation
    k_gemm_tc<__half><<<gemm_grid, 256, smemG>>>(B, wh + 32768, wl + 32768, disq, A, N, 1, tiles);
    k_gather_pool<<<gath_blocks, 256>>>(A, rowptr, csr, disq, b3, batch, sums, N);

    // fused MLP head
    k_mlp2<<<G, TD>>>(sums, Wm1, bm1, Wm2, bm2, gcnt, (float*)d_out);
}

// round 16
// speedup vs baseline: 1.2508x; 1.2508x over previous
#include <cuda_runtime.h>
#include <cuda_bf16.h>
#include <cuda_fp16.h>
#include <math.h>

#define TD 128
#define MAXN 50000
#define MAXE 1600000
#define MAXG 64
#define SCAN_B 256
#define MAXBLK ((MAXN + SCAN_B - 1) / SCAN_B)
#define AGGF 0x40000000u
#define PREF 0x80000000u
#define VMSK 0x3FFFFFFFu

// ---------------- scratch (static device globals; no allocations) -------------
__device__ __half g_Ah[MAXN * TD];       // GEMM output, rows pre-scaled by disq
__device__ __half g_Bh[MAXN * TD];       // gather output (pre-relu)
__device__ int   g_cnt[MAXN];
__device__ float g_disq[MAXN];
__device__ int   g_rowptr[MAXN + 1];
__device__ int   g_cursor[MAXN];
__device__ int   g_csr[MAXE];
__device__ unsigned g_stat[MAXBLK];      // lookback status: value | AGGF/PREF
__device__ float g_sums[MAXG * TD];
__device__ float g_gcnt[MAXG];
__device__ __nv_bfloat16 g_wh[3][TD * TD];   // W^T hi planes, [n][k] compact
__device__ __nv_bfloat16 g_wl[3][TD * TD];   // W^T lo planes

// ---------------- persistent stream/events (created pre-main; no device mem) ---
static cudaStream_t g_s2;
static cudaEvent_t g_evF, g_evD, g_evJ;
struct _InitOnce {
    _InitOnce() {
        cudaStreamCreateWithFlags(&g_s2, cudaStreamNonBlocking);
        cudaEventCreateWithFlags(&g_evF, cudaEventDisableTiming);
        cudaEventCreateWithFlags(&g_evD, cudaEventDisableTiming);
        cudaEventCreateWithFlags(&g_evJ, cudaEventDisableTiming);
    }
};
static _InitOnce _init_once;

// ---------------- fused init: zero cnt + pooled sums + gcnt + scan status ------
__global__ void k_init(int* __restrict__ cnt, float* __restrict__ sums,
                       float* __restrict__ gcnt, unsigned* __restrict__ stat,
                       int N, int G, int nb) {
    int i = blockIdx.x * blockDim.x + threadIdx.x;
    if (i < N) cnt[i] = 0;
    if (i < G * TD) sums[i] = 0.f;
    if (i < G) gcnt[i] = 0.f;
    if (i < nb) stat[i] = 0u;
}

// 4 edges per thread (MLP=4; these kernels are ATOMG-latency bound)
__global__ void k_count(const int* __restrict__ ei, int* __restrict__ cnt,
                        int E, int vec_ok) {
    int e0 = (blockIdx.x * blockDim.x + threadIdx.x) * 4;
    if (vec_ok && e0 + 3 < E) {
        int4 d = *(const int4*)(ei + E + e0);
        atomicAdd(&cnt[d.x], 1);
        atomicAdd(&cnt[d.y], 1);
        atomicAdd(&cnt[d.z], 1);
        atomicAdd(&cnt[d.w], 1);
    } else {
        #pragma unroll
        for (int q = 0; q < 4; q++)
            if (e0 + q < E) atomicAdd(&cnt[ei[E + e0 + q]], 1);
    }
}

// single-kernel decoupled-lookback exclusive scan (warp-parallel lookback)
// (+ disq, cursor copy, gcnt, rowptr[N] total — all fused)
__global__ void k_scan_lb(const int* __restrict__ cnt, int* __restrict__ rowptr,
                          int* __restrict__ cursor, float* __restrict__ disq,
                          const int* __restrict__ batch, float* __restrict__ gcnt,
                          unsigned* __restrict__ stat, int N, int nb) {
    __shared__ int wsum[8];
    __shared__ int s_exc;
    int t = threadIdx.x, bid = blockIdx.x;
    int i = bid * SCAN_B + t;
    int lane = t & 31, wid = t >> 5;

    int v = (i < N) ? cnt[i] : 0;
    if (i < N) disq[i] = rsqrtf((float)(v + 1));

    // intra-block scan
    int inc = v;
    #pragma unroll
    for (int off = 1; off < 32; off <<= 1) {
        int u = __shfl_up_sync(0xffffffffu, inc, off);
        if (lane >= off) inc += u;
    }
    if (lane == 31) wsum[wid] = inc;
    __syncthreads();
    if (wid == 0) {
        int w = (lane < 8) ? wsum[lane] : 0;
        #pragma unroll
        for (int off = 1; off < 8; off <<= 1) {
            int u = __shfl_up_sync(0xffffffffu, w, off);
            if (lane >= off) w += u;
        }
        if (lane < 8) wsum[lane] = w;
    }
    __syncthreads();
    int base = (wid > 0) ? wsum[wid - 1] : 0;
    int total = wsum[7];

    // decoupled lookback, warp 0, 32 predecessors per step
    if (wid == 0) {
        if (bid == 0) {
            if (lane == 0) {
                atomicExch(&stat[0], (unsigned)total | PREF);
                s_exc = 0;
            }
        } else {
            if (lane == 0) atomicExch(&stat[bid], (unsigned)total | AGGF);
            __syncwarp();
            int exc = 0;
            int p_hi = bid - 1;
            while (true) {
                int idx = p_hi - lane;                      // lane 0 = nearest pred
                unsigned s = (idx >= 0) ? *(volatile unsigned*)&stat[idx]
                                        : PREF;             // OOB = PREF, value 0
                bool ready = (s & (AGGF | PREF)) != 0u;
                if (__ballot_sync(0xffffffffu, ready) != 0xffffffffu) continue;
                unsigned pm = __ballot_sync(0xffffffffu, (s & PREF) != 0u);
                if (pm) {
                    int first = __ffs(pm) - 1;              // nearest PREF
                    int contrib = (lane <= first) ? (int)(s & VMSK) : 0;
                    #pragma unroll
                    for (int off = 16; off; off >>= 1)
                        contrib += __shfl_down_sync(0xffffffffu, contrib, off);
                    exc += __shfl_sync(0xffffffffu, contrib, 0);
                    break;
                } else {
                    int contrib = (int)(s & VMSK);
                    #pragma unroll
                    for (int off = 16; off; off >>= 1)
                        contrib += __shfl_down_sync(0xffffffffu, contrib, off);
                    exc += __shfl_sync(0xffffffffu, contrib, 0);
                    p_hi -= 32;
                }
            }
            if (lane == 0) {
                atomicExch(&stat[bid], (unsigned)(exc + total) | PREF);
                s_exc = exc;
            }
        }
    }
    __syncthreads();
    int exc = s_exc;

    if (i < N) {
        int r = exc + base + inc - v;
        rowptr[i] = r;
        cursor[i] = r;
    }
    if (bid == nb - 1 && t == 0) rowptr[N] = exc + total;

    // gcnt (batch sorted -> warp-uniform fast path)
    int g = (i < N) ? __ldg(&batch[i]) : -1;
    int g0 = __shfl_sync(0xffffffffu, g, 0);
    bool uni = __all_sync(0xffffffffu, g == g0);
    if (uni) {
        if (lane == 0 && g0 >= 0) {
            int base2 = bid * SCAN_B + (t & ~31);
            int cntw = min(N - base2, 32);
            asm volatile("red.global.add.f32 [%0], %1;" :: "l"(gcnt + g0), "f"((float)cntw) : "memory");
        }
    } else if (g >= 0) {
        asm volatile("red.global.add.f32 [%0], %1;" :: "l"(gcnt + g), "f"(1.0f) : "memory");
    }
}

// 4 edges per thread (MLP=4)
__global__ void k_fill(const int* __restrict__ ei, int* __restrict__ cursor,
                       int* __restrict__ csr, int E, int vec_ok) {
    int e0 = (blockIdx.x * blockDim.x + threadIdx.x) * 4;
    if (vec_ok && e0 + 3 < E) {
        int4 s = *(const int4*)(ei + e0);
        int4 d = *(const int4*)(ei + E + e0);
        int p0 = atomicAdd(&cursor[d.x], 1);
        int p1 = atomicAdd(&cursor[d.y], 1);
        int p2 = atomicAdd(&cursor[d.z], 1);
        int p3 = atomicAdd(&cursor[d.w], 1);
        csr[p0] = s.x; csr[p1] = s.y; csr[p2] = s.z; csr[p3] = s.w;
    } else {
        #pragma unroll
        for (int q = 0; q < 4; q++) {
            int e = e0 + q;
            if (e < E) {
                int pos = atomicAdd(&cursor[ei[E + e]], 1);
                csr[pos] = ei[e];
            }
        }
    }
}

// ---------------- W split/transpose prep: all 3 layers in one kernel -----------
__global__ void k_wprep3(const float* __restrict__ W1, const float* __restrict__ W2,
                         const float* __restrict__ W3, __nv_bfloat16* __restrict__ hi,
                         __nv_bfloat16* __restrict__ lo) {
    int idx = blockIdx.x * blockDim.x + threadIdx.x;
    int l = idx >> 14;
    int r = idx & 16383;
    const float* W = (l == 0) ? W1 : (l == 1) ? W2 : W3;
    int k = r >> 7, n = r & 127;
    float v = W[r];
    __nv_bfloat16 h = __float2bfloat16_rn(v);
    hi[l * 16384 + n * TD + k] = h;
    lo[l * 16384 + n * TD + k] = __float2bfloat16_rn(v - __bfloat162float(h));
}

// ---------------- gather: rows pre-scaled by disq[src]; pure sum ---------------
__device__ __forceinline__ void add_row(float4& a, uint2 raw) {
    float2 lo = __half22float2(*(half2*)&raw.x);
    float2 hi = __half22float2(*(half2*)&raw.y);
    a.x += lo.x; a.y += lo.y;
    a.z += hi.x; a.w += hi.y;
}

// returns disq[w] * (sum_{src in N(w)} h'[src] + h'[w]) + bias   (pre-relu)
__device__ __forceinline__ float4 agg_node(const __half* __restrict__ h,
                                           const int* __restrict__ rowptr,
                                           const int* __restrict__ csr,
                                           const float* __restrict__ disq,
                                           const float* __restrict__ bias,
                                           int w, int lane) {
    int beg = __ldg(&rowptr[w]);
    int end = __ldg(&rowptr[w + 1]);
    float dd = __ldg(&disq[w]);
    int c = lane * 4;

    float4 a0 = make_float4(0.f, 0.f, 0.f, 0.f);
    float4 a1 = make_float4(0.f, 0.f, 0.f, 0.f);
    uint2 sraw = *(const uint2*)(h + (long)w * TD + c);
    add_row(a0, sraw);   // self message (already scaled by disq[w])

    for (int base = beg; base < end; base += 32) {
        int e = base + lane;
        int sidx = (e < end) ? __ldg(&csr[e]) : 0;
        int m = end - base; if (m > 32) m = 32;
        int j = 0;
        for (; j + 7 < m; j += 8) {
            int si[8]; uint2 vv[8];
            #pragma unroll
            for (int q = 0; q < 8; q++)
                si[q] = __shfl_sync(0xffffffffu, sidx, j + q);
            #pragma unroll
            for (int q = 0; q < 8; q++)
                vv[q] = *(const uint2*)(h + (long)si[q] * TD + c);
            #pragma unroll
            for (int q = 0; q < 8; q += 2) {
                add_row(a0, vv[q]);
                add_row(a1, vv[q + 1]);
            }
        }
        for (; j + 1 < m; j += 2) {
            int s0 = __shfl_sync(0xffffffffu, sidx, j);
            int s1 = __shfl_sync(0xffffffffu, sidx, j + 1);
            uint2 v0 = *(const uint2*)(h + (long)s0 * TD + c);
            uint2 v1 = *(const uint2*)(h + (long)s1 * TD + c);
            add_row(a0, v0);
            add_row(a1, v1);
        }
        if (j < m) {
            int s0 = __shfl_sync(0xffffffffu, sidx, j);
            uint2 v0 = *(const uint2*)(h + (long)s0 * TD + c);
            add_row(a0, v0);
        }
    }
    float4 bb = *(const float4*)(bias + c);
    return make_float4(fmaf(a0.x + a1.x, dd, bb.x), fmaf(a0.y + a1.y, dd, bb.y),
                       fmaf(a0.z + a1.z, dd, bb.z), fmaf(a0.w + a1.w, dd, bb.w));
}

// gather -> fp16 output (pre-relu; relu applied at next GEMM load)
__global__ void k_gather(const __half* __restrict__ h, const int* __restrict__ rowptr,
                         const int* __restrict__ csr, const float* __restrict__ disq,
                         const float* __restrict__ bias, __half* __restrict__ out, int N) {
    int w = (blockIdx.x * blockDim.x + threadIdx.x) >> 5;
    int lane = threadIdx.x & 31;
    if (w >= N) return;
    float4 r = agg_node(h, rowptr, csr, disq, bias, w, lane);
    half2 lo = __float22half2_rn(make_float2(r.x, r.y));
    half2 hi = __float22half2_rn(make_float2(r.z, r.w));
    uint2 o;
    o.x = *(unsigned*)&lo;
    o.y = *(unsigned*)&hi;
    *(uint2*)(out + (long)w * TD + lane * 4) = o;
}

// layer-3 variant: accumulate straight into pooled fp32 sums
__global__ void k_gather_pool(const __half* __restrict__ h, const int* __restrict__ rowptr,
                              const int* __restrict__ csr, const float* __restrict__ disq,
                              const float* __restrict__ bias, const int* __restrict__ batch,
                              float* __restrict__ sums, int N) {
    int w = (blockIdx.x * blockDim.x + threadIdx.x) >> 5;
    int lane = threadIdx.x & 31;
    if (w >= N) return;
    float4 r = agg_node(h, rowptr, csr, disq, bias, w, lane);
    int g = __ldg(&batch[w]);
    float* p = sums + (long)g * TD + lane * 4;
    asm volatile("red.global.add.v4.f32 [%0], {%1, %2, %3, %4};"
                 :: "l"(p), "f"(r.x), "f"(r.y), "f"(r.z), "f"(r.w) : "memory");
}

// ---------------- tensor-core GEMM (3-pass bf16 split; epilogue scales by disq) -
__device__ __forceinline__ unsigned pk_bf16x2(float hi, float lo) {
    unsigned d;
    asm("cvt.rn.bf16x2.f32 %0, %1, %2;" : "=r"(d) : "f"(hi), "f"(lo));
    return d;
}

__device__ __forceinline__ void mma_bf16(float* c, const unsigned* a, unsigned b0, unsigned b1) {
    asm volatile(
        "mma.sync.aligned.m16n8k16.row.col.f32.bf16.bf16.f32 "
        "{%0,%1,%2,%3}, {%4,%5,%6,%7}, {%8,%9}, {%0,%1,%2,%3};"
        : "+f"(c[0]), "+f"(c[1]), "+f"(c[2]), "+f"(c[3])
        : "r"(a[0]), "r"(a[1]), "r"(a[2]), "r"(a[3]), "r"(b0), "r"(b1));
}

__device__ __forceinline__ float4 ldx4(const float* p) { return *(const float4*)p; }
__device__ __forceinline__ float4 ldx4(const __half* p) {
    uint2 raw = *(const uint2*)p;
    float2 lo = __half22float2(*(half2*)&raw.x);
    float2 hi = __half22float2(*(half2*)&raw.y);
    return make_float4(lo.x, lo.y, hi.x, hi.y);
}

#define XS 136
#define WSZ (64 * XS)
#define WTS 136

template <typename T>
__global__ void __launch_bounds__(256) k_gemm_tc(const T* __restrict__ X,
                                                 const __nv_bfloat16* __restrict__ whg,
                                                 const __nv_bfloat16* __restrict__ wlg,
                                                 const float* __restrict__ disq,
                                                 __half* __restrict__ C,
                                                 int M, int do_relu) {
    extern __shared__ char smraw[];
    float* xs = (float*)smraw;                                    // [64][136] fp32
    __nv_bfloat16* wh = (__nv_bfloat16*)(smraw + WSZ * 4);        // [128][136] hi (n,k)
    __nv_bfloat16* wl = wh + 128 * WTS;                           // lo plane

    int tid = threadIdx.x;
    int row0 = blockIdx.x * 64;

    for (int idx = tid; idx < 2048; idx += 256) {
        int row = idx >> 4;
        int cc = (idx & 15) * 8;
        *(float4*)(wh + row * WTS + cc) = *(const float4*)(whg + row * TD + cc);
        *(float4*)(wl + row * WTS + cc) = *(const float4*)(wlg + row * TD + cc);
    }
    for (int i = tid * 4; i < 64 * TD; i += 1024) {
        int r = i >> 7;
        int cc = i & 127;
        int gr = row0 + r;
        float4 v = make_float4(0.f, 0.f, 0.f, 0.f);
        if (gr < M) v = ldx4(X + (long)gr * TD + cc);
        if (do_relu) {
            v.x = fmaxf(v.x, 0.f); v.y = fmaxf(v.y, 0.f);
            v.z = fmaxf(v.z, 0.f); v.w = fmaxf(v.w, 0.f);
        }
        *(float4*)(xs + r * XS + cc) = v;
    }
    __syncthreads();

    int warp = tid >> 5;
    int lane = tid & 31;
    int gid = lane >> 2;
    int tig = lane & 3;
    int r0 = 16 * (warp >> 1);
    int c0 = 64 * (warp & 1);

    float acc[8][4];
    #pragma unroll
    for (int t = 0; t < 8; t++)
        #pragma unroll
        for (int q = 0; q < 4; q++) acc[t][q] = 0.f;

    #pragma unroll
    for (int k0 = 0; k0 < TD; k0 += 16) {
        float2 p0 = *(float2*)&xs[(r0 + gid) * XS + k0 + 2 * tig];
        float2 p1 = *(float2*)&xs[(r0 + gid + 8) * XS + k0 + 2 * tig];
        float2 p2 = *(float2*)&xs[(r0 + gid) * XS + k0 + 8 + 2 * tig];
        float2 p3 = *(float2*)&xs[(r0 + gid + 8) * XS + k0 + 8 + 2 * tig];
        unsigned ah[4], al[4];
        float2 pp[4] = {p0, p1, p2, p3};
        #pragma unroll
        for (int i = 0; i < 4; i++) {
            unsigned h = pk_bf16x2(pp[i].y, pp[i].x);
            ah[i] = h;
            float hx = __uint_as_float(h << 16);
            float hy = __uint_as_float(h & 0xffff0000u);
            al[i] = pk_bf16x2(pp[i].y - hy, pp[i].x - hx);
        }
        #pragma unroll
        for (int t = 0; t < 8; t++) {
            int n = c0 + 8 * t + gid;
            unsigned bh0 = *(const unsigned*)&wh[n * WTS + k0 + 2 * tig];
            unsigned bh1 = *(const unsigned*)&wh[n * WTS + k0 + 8 + 2 * tig];
            unsigned bl0 = *(const unsigned*)&wl[n * WTS + k0 + 2 * tig];
            unsigned bl1 = *(const unsigned*)&wl[n * WTS + k0 + 8 + 2 * tig];
            mma_bf16(acc[t], ah, bh0, bh1);
            mma_bf16(acc[t], al, bh0, bh1);
            mma_bf16(acc[t], ah, bl0, bl1);
        }
    }

    int gr = row0 + r0 + gid;
    int gr2 = gr + 8;
    float s1 = (gr < M) ? __ldg(&disq[gr]) : 0.f;
    float s2 = (gr2 < M) ? __ldg(&disq[gr2]) : 0.f;
    #pragma unroll
    for (int t = 0; t < 8; t++) {
        int col = c0 + 8 * t + 2 * tig;
        if (gr < M) {
            half2 o = __float22half2_rn(make_float2(acc[t][0] * s1, acc[t][1] * s1));
            *(half2*)&C[(long)gr * TD + col] = o;
        }
        if (gr2 < M) {
            half2 o = __float22half2_rn(make_float2(acc[t][2] * s2, acc[t][3] * s2));
            *(half2*)&C[(long)gr2 * TD + col] = o;
        }
    }
}

// ---------------- fused 2-layer MLP head (per-graph independent) ----------------
__global__ void k_mlp2(const float* __restrict__ in,
                       const float* __restrict__ Wm1, const float* __restrict__ bm1,
                       const float* __restrict__ Wm2, const float* __restrict__ bm2,
                       const float* __restrict__ gcnt, float* __restrict__ out) {
    __shared__ float p[TD];
    __shared__ float q[TD];
    int g = blockIdx.x, j = threadIdx.x;
    float scale = 1.0f / fmaxf(gcnt[g], 1.0f);
    p[j] = in[g * TD + j] * scale;
    __syncthreads();
    float acc = bm1[j];
    #pragma unroll 8
    for (int k = 0; k < TD; k++) acc = fmaf(p[k], Wm1[k * TD + j], acc);
    q[j] = fmaxf(acc, 0.f);
    __syncthreads();
    float acc2 = bm2[j];
    #pragma unroll 8
    for (int k = 0; k < TD; k++) acc2 = fmaf(q[k], Wm2[k * TD + j], acc2);
    out[g * TD + j] = acc2;
}

// ---------------- launch --------------------------------------------------------
extern "C" void kernel_launch(void* const* d_in, const int* in_sizes, int n_in,
                              void* d_out, int out_size) {
    const float* x   = (const float*)d_in[0];
    const float* W1  = (const float*)d_in[1];
    const float* b1  = (const float*)d_in[2];
    const float* W2  = (const float*)d_in[3];
    const float* b2  = (const float*)d_in[4];
    const float* W3  = (const float*)d_in[5];
    const float* b3  = (const float*)d_in[6];
    const float* Wm1 = (const float*)d_in[7];
    const float* bm1 = (const float*)d_in[8];
    const float* Wm2 = (const float*)d_in[9];
    const float* bm2 = (const float*)d_in[10];
    const int* ei    = (const int*)d_in[11];
    const int* batch = (const int*)d_in[12];

    int N = in_sizes[0] / TD;
    int E = in_sizes[11] / 2;
    int G = out_size / TD;
    int vec_ok = ((E & 3) == 0) ? 1 : 0;

    float *disq, *sums, *gcnt;
    __half *A, *B;
    int *cnt, *rowptr, *cursor, *csr;
    unsigned* stat;
    __nv_bfloat16 *wh, *wl;
    cudaGetSymbolAddress((void**)&A,      g_Ah);
    cudaGetSymbolAddress((void**)&B,      g_Bh);
    cudaGetSymbolAddress((void**)&cnt,    g_cnt);
    cudaGetSymbolAddress((void**)&disq,   g_disq);
    cudaGetSymbolAddress((void**)&rowptr, g_rowptr);
    cudaGetSymbolAddress((void**)&cursor, g_cursor);
    cudaGetSymbolAddress((void**)&csr,    g_csr);
    cudaGetSymbolAddress((void**)&stat,   g_stat);
    cudaGetSymbolAddress((void**)&sums,   g_sums);
    cudaGetSymbolAddress((void**)&gcnt,   g_gcnt);
    cudaGetSymbolAddress((void**)&wh,     g_wh);
    cudaGetSymbolAddress((void**)&wl,     g_wl);

    size_t smemG = (size_t)WSZ * 4 + 2 * (size_t)(128 * WTS) * 2;   // 104448 B
    cudaFuncSetAttribute(k_gemm_tc<float>, cudaFuncAttributeMaxDynamicSharedMemorySize, (int)smemG);
    cudaFuncSetAttribute(k_gemm_tc<__half>, cudaFuncAttributeMaxDynamicSharedMemorySize, (int)smemG);

    int nb = (N + SCAN_B - 1) / SCAN_B;
    int gemm_blocks = (N + 63) / 64;
    int gath_blocks = (N + 7) / 8;
    int edge4_blocks = (E + 1023) / 1024;

    // ---- fork: CSR build on side stream; W-prep on main -----------------------
    cudaEventRecord(g_evF, 0);
    cudaStreamWaitEvent(g_s2, g_evF, 0);

    k_init<<<(N + 255) / 256, 256, 0, g_s2>>>(cnt, sums, gcnt, stat, N, G, nb);
    k_count<<<edge4_blocks, 256, 0, g_s2>>>(ei, cnt, E, vec_ok);
    k_scan_lb<<<nb, SCAN_B, 0, g_s2>>>(cnt, rowptr, cursor, disq, batch, gcnt, stat, N, nb);
    cudaEventRecord(g_evD, g_s2);                         // disq ready
    k_fill<<<edge4_blocks, 256, 0, g_s2>>>(ei, cursor, csr, E, vec_ok);
    cudaEventRecord(g_evJ, g_s2);                         // CSR ready

    // main branch
    k_wprep3<<<192, 256>>>(W1, W2, W3, wh, wl);
    cudaStreamWaitEvent(0, g_evD, 0);                     // GEMM epilogue needs disq
    k_gemm_tc<float><<<gemm_blocks, 256, smemG>>>(x, wh, wl, disq, A, N, 0);

    cudaStreamWaitEvent(0, g_evJ, 0);                     // gathers need CSR

    // layer 1
    k_gather<<<gath_blocks, 256>>>(A, rowptr, csr, disq, b1, B, N);
    // layer 2
    k_gemm_tc<__half><<<gemm_blocks, 256, smemG>>>(B, wh + 16384, wl + 16384, disq, A, N, 1);
    k_gather<<<gath_blocks, 256>>>(A, rowptr, csr, disq, b2, B, N);
    // layer 3: gather fused with mean-pool accumulation
    k_gemm_tc<__half><<<gemm_blocks, 256, smemG>>>(B, wh + 32768, wl + 32768, disq, A, N, 1);
    k_gather_pool<<<gath_blocks, 256>>>(A, rowptr, csr, disq, b3, batch, sums, N);

    // fused MLP head
    k_mlp2<<<G, TD>>>(sums, Wm1, bm1, Wm2, bm2, gcnt, (float*)d_out);
}